// round 3
// baseline (speedup 1.0000x reference)
#include <cuda_runtime.h>
#include <math.h>

#define B_  4
#define S_  2048
#define C_  1024
#define H_  16
#define D_  64
#define M_  (B_*S_)     // 8192
#define N3_ (3*C_)      // 3072

// Scratch (no allocations allowed): q/k/v in [B,H,S,D], attn output in [B,S,C]
__device__ float g_q [B_*H_*S_*D_];
__device__ float g_k [B_*H_*S_*D_];
__device__ float g_v [B_*H_*S_*D_];
__device__ float g_ao[M_*C_];

// ---------------------------------------------------------------------------
// GEMM 1: QKV = x @ W_attn + b_attn, scattered into q/k/v [B,H,S,D]
// 128x128 tile, BK=16, 256 threads, 8x8 per-thread.
// ---------------------------------------------------------------------------
__global__ __launch_bounds__(256) void qkv_gemm(
    const float* __restrict__ X, const float* __restrict__ W,
    const float* __restrict__ bias)
{
    __shared__ float As[16][132];   // transposed A: As[k][m]
    __shared__ float Bs[16][128];   // Bs[k][n]
    const int tid = threadIdx.x;
    const int ty  = tid >> 4, tx = tid & 15;
    const int m0  = blockIdx.y << 7;
    const int n0  = blockIdx.x << 7;

    float acc[8][8];
#pragma unroll
    for (int i = 0; i < 8; i++)
#pragma unroll
        for (int j = 0; j < 8; j++) acc[i][j] = 0.f;

    for (int k0 = 0; k0 < C_; k0 += 16) {
#pragma unroll
        for (int i = 0; i < 2; i++) {
            int f  = tid * 2 + i;
            int ar = f >> 2;                 // 0..127
            int ac = (f & 3) << 2;           // 0,4,8,12
            float4 av = *(const float4*)(X + (size_t)(m0 + ar) * C_ + k0 + ac);
            As[ac+0][ar] = av.x; As[ac+1][ar] = av.y;
            As[ac+2][ar] = av.z; As[ac+3][ar] = av.w;
            int br = f >> 5;                 // 0..15
            int bc = (f & 31) << 2;          // 0..124
            *(float4*)&Bs[br][bc] =
                *(const float4*)(W + (size_t)(k0 + br) * N3_ + n0 + bc);
        }
        __syncthreads();
#pragma unroll
        for (int k = 0; k < 16; k++) {
            float a[8], b[8];
            *(float4*)&a[0] = *(const float4*)&As[k][ty*8];
            *(float4*)&a[4] = *(const float4*)&As[k][ty*8 + 4];
            *(float4*)&b[0] = *(const float4*)&Bs[k][tx*8];
            *(float4*)&b[4] = *(const float4*)&Bs[k][tx*8 + 4];
#pragma unroll
            for (int i = 0; i < 8; i++)
#pragma unroll
                for (int j = 0; j < 8; j++)
                    acc[i][j] = fmaf(a[i], b[j], acc[i][j]);
        }
        __syncthreads();
    }

    // Epilogue: bias + scatter to q/k/v. 128-wide n tile lies fully inside one
    // of the three parts (C_ multiple of 128), so 'part' is block-uniform.
    const int part = n0 >> 10;
    float* dst = (part == 0) ? g_q : (part == 1) ? g_k : g_v;
#pragma unroll
    for (int i = 0; i < 8; i++) {
        int m  = m0 + ty*8 + i;
        int bb = m >> 11;            // / S_
        int ss = m & (S_ - 1);
#pragma unroll
        for (int j = 0; j < 8; j++) {
            int n = n0 + tx*8 + j;
            int c = n & (C_ - 1);
            int h = c >> 6;
            int d = c & 63;
            dst[(((size_t)(bb*H_ + h))*S_ + ss)*D_ + d] = acc[i][j] + bias[n];
        }
    }
}

// ---------------------------------------------------------------------------
// GEMM 2: out = g_ao @ W_proj + b_proj   (row-major [M_, C_] output)
// ---------------------------------------------------------------------------
__global__ __launch_bounds__(256) void proj_gemm(
    const float* __restrict__ W, const float* __restrict__ bias,
    float* __restrict__ out)
{
    __shared__ float As[16][132];
    __shared__ float Bs[16][128];
    const int tid = threadIdx.x;
    const int ty  = tid >> 4, tx = tid & 15;
    const int m0  = blockIdx.y << 7;
    const int n0  = blockIdx.x << 7;

    float acc[8][8];
#pragma unroll
    for (int i = 0; i < 8; i++)
#pragma unroll
        for (int j = 0; j < 8; j++) acc[i][j] = 0.f;

    for (int k0 = 0; k0 < C_; k0 += 16) {
#pragma unroll
        for (int i = 0; i < 2; i++) {
            int f  = tid * 2 + i;
            int ar = f >> 2;
            int ac = (f & 3) << 2;
            float4 av = *(const float4*)(g_ao + (size_t)(m0 + ar) * C_ + k0 + ac);
            As[ac+0][ar] = av.x; As[ac+1][ar] = av.y;
            As[ac+2][ar] = av.z; As[ac+3][ar] = av.w;
            int br = f >> 5;
            int bc = (f & 31) << 2;
            *(float4*)&Bs[br][bc] =
                *(const float4*)(W + (size_t)(k0 + br) * C_ + n0 + bc);
        }
        __syncthreads();
#pragma unroll
        for (int k = 0; k < 16; k++) {
            float a[8], b[8];
            *(float4*)&a[0] = *(const float4*)&As[k][ty*8];
            *(float4*)&a[4] = *(const float4*)&As[k][ty*8 + 4];
            *(float4*)&b[0] = *(const float4*)&Bs[k][tx*8];
            *(float4*)&b[4] = *(const float4*)&Bs[k][tx*8 + 4];
#pragma unroll
            for (int i = 0; i < 8; i++)
#pragma unroll
                for (int j = 0; j < 8; j++)
                    acc[i][j] = fmaf(a[i], b[j], acc[i][j]);
        }
        __syncthreads();
    }

#pragma unroll
    for (int i = 0; i < 8; i++) {
        int m = m0 + ty*8 + i;
        float4 o0, o1;
        o0.x = acc[i][0] + bias[n0 + tx*8 + 0];
        o0.y = acc[i][1] + bias[n0 + tx*8 + 1];
        o0.z = acc[i][2] + bias[n0 + tx*8 + 2];
        o0.w = acc[i][3] + bias[n0 + tx*8 + 3];
        o1.x = acc[i][4] + bias[n0 + tx*8 + 4];
        o1.y = acc[i][5] + bias[n0 + tx*8 + 5];
        o1.z = acc[i][6] + bias[n0 + tx*8 + 6];
        o1.w = acc[i][7] + bias[n0 + tx*8 + 7];
        *(float4*)(out + (size_t)m * C_ + n0 + tx*8)     = o0;
        *(float4*)(out + (size_t)m * C_ + n0 + tx*8 + 4) = o1;
    }
}

// ---------------------------------------------------------------------------
// Flash attention (causal, fp32, online softmax).
// Block: 256 threads (16x16), 64 queries x 64 keys per tile, D=64.
// SMEM: exactly 48KB, rotation-swizzled rows: elem (x,y) -> x*64 + ((y+x)&63).
// Row r is owned by the 16 contiguous lanes sharing ty -> shfl width-16 reduce.
// ---------------------------------------------------------------------------
#define SIDX(x,y) (((x) << 6) | (((y) + (x)) & 63))

__global__ __launch_bounds__(256) void flash_attn()
{
    __shared__ float Qs [4096];   // [d][r]
    __shared__ float KPs[4096];   // K^T [d][j], then P^T [j][r]
    __shared__ float Vs [4096];   // [j][d]

    const int tid = threadIdx.x;
    const int ty  = tid >> 4, tx = tid & 15;
    const int bh  = blockIdx.y;
    const int q0  = blockIdx.x << 6;

    const float* Qp = g_q + (size_t)bh * S_ * D_;
    const float* Kp = g_k + (size_t)bh * S_ * D_;
    const float* Vp = g_v + (size_t)bh * S_ * D_;

    // Load Q tile transposed: Qs[d][r]
#pragma unroll
    for (int i = 0; i < 4; i++) {
        int f  = tid + (i << 8);
        int r  = f >> 4;
        int d4 = (f & 15) << 2;
        float4 qv = *(const float4*)(Qp + (size_t)(q0 + r) * D_ + d4);
        Qs[SIDX(d4+0, r)] = qv.x; Qs[SIDX(d4+1, r)] = qv.y;
        Qs[SIDX(d4+2, r)] = qv.z; Qs[SIDX(d4+3, r)] = qv.w;
    }

    float m_i[4], l_i[4], acc[4][4];
#pragma unroll
    for (int i = 0; i < 4; i++) {
        m_i[i] = -1e30f; l_i[i] = 0.f;
#pragma unroll
        for (int j = 0; j < 4; j++) acc[i][j] = 0.f;
    }

    const int ntiles = blockIdx.x + 1;   // causal: key tiles 0..qtile
    const float scale = 0.125f;          // 1/sqrt(64)

    for (int t = 0; t < ntiles; t++) {
        const int k0 = t << 6;
        // Load K (transposed) and V tiles
#pragma unroll
        for (int i = 0; i < 4; i++) {
            int f  = tid + (i << 8);
            int r  = f >> 4;
            int d4 = (f & 15) << 2;
            float4 kv = *(const float4*)(Kp + (size_t)(k0 + r) * D_ + d4);
            KPs[SIDX(d4+0, r)] = kv.x; KPs[SIDX(d4+1, r)] = kv.y;
            KPs[SIDX(d4+2, r)] = kv.z; KPs[SIDX(d4+3, r)] = kv.w;
            float4 vv = *(const float4*)(Vp + (size_t)(k0 + r) * D_ + d4);
            Vs[SIDX(r, d4+0)] = vv.x; Vs[SIDX(r, d4+1)] = vv.y;
            Vs[SIDX(r, d4+2)] = vv.z; Vs[SIDX(r, d4+3)] = vv.w;
        }
        __syncthreads();

        // S = Q @ K^T  (16 FMA / 8 LDS per d-step per thread)
        float s[4][4];
#pragma unroll
        for (int i = 0; i < 4; i++)
#pragma unroll
            for (int j = 0; j < 4; j++) s[i][j] = 0.f;
        for (int d = 0; d < 64; d++) {
            float qf[4], kf[4];
#pragma unroll
            for (int c = 0; c < 4; c++) {
                qf[c] = Qs [SIDX(d, ty*4 + c)];
                kf[c] = KPs[SIDX(d, tx*4 + c)];
            }
#pragma unroll
            for (int i = 0; i < 4; i++)
#pragma unroll
                for (int j = 0; j < 4; j++)
                    s[i][j] = fmaf(qf[i], kf[j], s[i][j]);
        }

        // Scale + causal mask (only the diagonal tile needs masking)
        const bool diag = (t == ntiles - 1);
#pragma unroll
        for (int i = 0; i < 4; i++)
#pragma unroll
            for (int j = 0; j < 4; j++) {
                float sv = s[i][j] * scale;
                if (diag && (k0 + tx*4 + j > q0 + ty*4 + i)) sv = -1e30f;
                s[i][j] = sv;
            }

        // Online softmax update
        float p[4][4];
#pragma unroll
        for (int i = 0; i < 4; i++) {
            float v = fmaxf(fmaxf(s[i][0], s[i][1]), fmaxf(s[i][2], s[i][3]));
#pragma unroll
            for (int off = 8; off > 0; off >>= 1)
                v = fmaxf(v, __shfl_xor_sync(0xffffffffu, v, off, 16));
            float mn   = fmaxf(m_i[i], v);
            float corr = __expf(m_i[i] - mn);
            m_i[i] = mn;
            float rs = 0.f;
#pragma unroll
            for (int j = 0; j < 4; j++) {
                p[i][j] = __expf(s[i][j] - mn);
                rs += p[i][j];
            }
#pragma unroll
            for (int off = 8; off > 0; off >>= 1)
                rs += __shfl_xor_sync(0xffffffffu, rs, off, 16);
            l_i[i] = l_i[i] * corr + rs;
#pragma unroll
            for (int j = 0; j < 4; j++) acc[i][j] *= corr;
        }

        __syncthreads();   // all threads done reading K tile
        // Store P transposed: KPs[j][r]
#pragma unroll
        for (int j = 0; j < 4; j++)
#pragma unroll
            for (int i = 0; i < 4; i++)
                KPs[SIDX(tx*4 + j, ty*4 + i)] = p[i][j];
        __syncthreads();

        // O += P @ V
        for (int jj = 0; jj < 64; jj++) {
            float pf[4], vf[4];
#pragma unroll
            for (int c = 0; c < 4; c++) {
                pf[c] = KPs[SIDX(jj, ty*4 + c)];
                vf[c] = Vs [SIDX(jj, tx*4 + c)];
            }
#pragma unroll
            for (int i = 0; i < 4; i++)
#pragma unroll
                for (int j = 0; j < 4; j++)
                    acc[i][j] = fmaf(pf[i], vf[j], acc[i][j]);
        }
        __syncthreads();   // before next tile overwrites KPs/Vs
    }

    // Normalize and write to g_ao[B,S,C] with c = h*64 + d
    const int bb = bh >> 4;     // / H_
    const int h  = bh & 15;
#pragma unroll
    for (int i = 0; i < 4; i++) {
        float inv = 1.f / l_i[i];
        float4 o;
        o.x = acc[i][0] * inv; o.y = acc[i][1] * inv;
        o.z = acc[i][2] * inv; o.w = acc[i][3] * inv;
        *(float4*)(g_ao + ((size_t)bb * S_ + q0 + ty*4 + i) * C_
                         + h * D_ + tx*4) = o;
    }
}

// ---------------------------------------------------------------------------
// Launch: inputs per metadata order: x, W_attn, b_attn, W_proj, b_proj
// ---------------------------------------------------------------------------
extern "C" void kernel_launch(void* const* d_in, const int* in_sizes, int n_in,
                              void* d_out, int out_size)
{
    (void)in_sizes; (void)n_in; (void)out_size;
    const float* x      = (const float*)d_in[0];
    const float* W_attn = (const float*)d_in[1];
    const float* b_attn = (const float*)d_in[2];
    const float* W_proj = (const float*)d_in[3];
    const float* b_proj = (const float*)d_in[4];
    float* out = (float*)d_out;

    qkv_gemm <<<dim3(N3_/128, M_/128), 256>>>(x, W_attn, b_attn);
    flash_attn<<<dim3(S_/64, B_*H_), 256>>>();
    proj_gemm <<<dim3(C_/128, M_/128), 256>>>(W_proj, b_proj, out);
}

// round 4
// speedup vs baseline: 1.3888x; 1.3888x over previous
#include <cuda_runtime.h>
#include <cuda_bf16.h>

#define B_  4
#define S_  2048
#define C_  1024
#define H_  16
#define D_  64
#define M_  (B_*S_)     // 8192
#define N3_ (3*C_)      // 3072

// Scratch (no allocations allowed)
__device__ float g_q [B_*H_*S_*D_];
__device__ float g_k [B_*H_*S_*D_];
__device__ float g_v [B_*H_*S_*D_];
__device__ float g_ao[M_*C_];

// ---------------------------------------------------------------------------
// helpers
// ---------------------------------------------------------------------------
__device__ __forceinline__ unsigned pk2(float a, float b) {
    __nv_bfloat162 t = __floats2bfloat162_rn(a, b);
    return *reinterpret_cast<const unsigned*>(&t);
}
__device__ __forceinline__ float bfhi(float x) {
    return __bfloat162float(__float2bfloat16_rn(x));
}
__device__ __forceinline__ void ldsm4(unsigned r[4], unsigned addr) {
    asm volatile("ldmatrix.sync.aligned.m8n8.x4.shared.b16 {%0,%1,%2,%3}, [%4];\n"
        : "=r"(r[0]), "=r"(r[1]), "=r"(r[2]), "=r"(r[3]) : "r"(addr));
}
__device__ __forceinline__ void ldsm2t(unsigned r[2], unsigned addr) {
    asm volatile("ldmatrix.sync.aligned.m8n8.x2.trans.shared.b16 {%0,%1}, [%2];\n"
        : "=r"(r[0]), "=r"(r[1]) : "r"(addr));
}
__device__ __forceinline__ void mma16816(float c[4], const unsigned a[4],
                                         const unsigned b[2]) {
    asm volatile(
        "mma.sync.aligned.m16n8k16.row.col.f32.bf16.bf16.f32 "
        "{%0,%1,%2,%3}, {%4,%5,%6,%7}, {%8,%9}, {%0,%1,%2,%3};\n"
        : "+f"(c[0]), "+f"(c[1]), "+f"(c[2]), "+f"(c[3])
        : "r"(a[0]), "r"(a[1]), "r"(a[2]), "r"(a[3]), "r"(b[0]), "r"(b[1]));
}

// ---------------------------------------------------------------------------
// Tensor-core GEMM with bf16 hi/lo split (3x MMA ~ fp32 accuracy).
// C[m,n] = A[m,:] @ W[:,n] + bias[n]. A stride = C_. LDB = W row stride.
// Block 128x128, BK=32, 256 threads (8 warps, 2m x 4n of 64x32 warp tiles).
// SCATTER=true: scatter into g_q/g_k/g_v [B,H,S,D]; else write out[m*C_+n].
// ---------------------------------------------------------------------------
template<int LDB, bool SCATTER>
__global__ __launch_bounds__(256) void tc_gemm(
    const float* __restrict__ Ain, const float* __restrict__ W,
    const float* __restrict__ bias, float* __restrict__ out)
{
    // A: [0,16384): 128 rows x 128B (chunks 0-3: hi k0..31, chunks 4-7: lo)
    // Bh: [16384,24576): 32 k-rows x 256B; Bl: [24576,32768)
    __shared__ __align__(16) unsigned char smem[32768];
    unsigned char* smemc = smem;
    const unsigned sA  = (unsigned)__cvta_generic_to_shared(smem);
    const unsigned sBh = sA + 16384;
    const unsigned sBl = sA + 24576;

    const float* __restrict__ A = SCATTER ? Ain : (const float*)g_ao;

    const int tid  = threadIdx.x;
    const int lane = tid & 31, warp = tid >> 5;
    const int mw = warp & 1, nw = warp >> 1;         // 2 x 4 warp grid
    const int m0 = blockIdx.y << 7, n0 = blockIdx.x << 7;

    // global load coords (4 float4 each for A and B per thread per BK step)
    const float* aPtr[4]; const float* bPtr[4];
    unsigned aOffH[4], aOffL[4], bOff[4];
#pragma unroll
    for (int i = 0; i < 4; i++) {
        int f = i * 256 + tid;
        int ar = f >> 3, akq = (f & 7) << 2;          // row 0..127, k 0..28
        aPtr[i] = A + (size_t)(m0 + ar) * C_ + akq;
        aOffH[i] = ar * 128 + ((( (akq >> 3))     ^ (ar & 7)) << 4) + ((akq & 7) << 1);
        aOffL[i] = ar * 128 + (((4 + (akq >> 3))  ^ (ar & 7)) << 4) + ((akq & 7) << 1);
        int bk = f >> 5, bnq = (f & 31) << 2;         // k 0..31, n 0..124
        bPtr[i] = W + (size_t)bk * LDB + n0 + bnq;
        bOff[i] = bk * 256 + (((bnq >> 3) ^ (bk & 7)) << 4) + ((bnq & 7) << 1);
    }

    float acc[16][4];
#pragma unroll
    for (int i = 0; i < 16; i++)
#pragma unroll
        for (int j = 0; j < 4; j++) acc[i][j] = 0.f;

    // fragment address components
    const int aRowF = mw * 64 + (lane & 15);          // + mt*16
    const int aKh   = lane >> 4;                      // 0/1 (k half of 16)
    const int bKL   = lane & 15;                      // + ks*16
    const int bC    = nw * 4;                         // chunk base, + nt

    float4 pa[4], pb[4];
#pragma unroll
    for (int i = 0; i < 4; i++) { pa[i] = *(const float4*)aPtr[i];
                                  pb[i] = *(const float4*)bPtr[i]; }

    for (int kt = 0; kt < C_ / 32; kt++) {
        // store current tile (hi/lo split) to smem
#pragma unroll
        for (int i = 0; i < 4; i++) {
            float h0 = bfhi(pa[i].x), h1 = bfhi(pa[i].y);
            float h2 = bfhi(pa[i].z), h3 = bfhi(pa[i].w);
            *(uint2*)(smemc + aOffH[i]) = make_uint2(pk2(h0, h1), pk2(h2, h3));
            *(uint2*)(smemc + aOffL[i]) = make_uint2(
                pk2(pa[i].x - h0, pa[i].y - h1), pk2(pa[i].z - h2, pa[i].w - h3));
            float g0 = bfhi(pb[i].x), g1 = bfhi(pb[i].y);
            float g2 = bfhi(pb[i].z), g3 = bfhi(pb[i].w);
            *(uint2*)(smemc + 16384 + bOff[i]) = make_uint2(pk2(g0, g1), pk2(g2, g3));
            *(uint2*)(smemc + 24576 + bOff[i]) = make_uint2(
                pk2(pb[i].x - g0, pb[i].y - g1), pk2(pb[i].z - g2, pb[i].w - g3));
        }
        __syncthreads();

        if (kt + 1 < C_ / 32) {
#pragma unroll
            for (int i = 0; i < 4; i++) {
                aPtr[i] += 32;
                bPtr[i] += (size_t)32 * LDB;
                pa[i] = *(const float4*)aPtr[i];
                pb[i] = *(const float4*)bPtr[i];
            }
        }

#pragma unroll
        for (int ks = 0; ks < 2; ks++) {
            unsigned ah[4][4], al[4][4], bh[4][2], bl[4][2];
#pragma unroll
            for (int mt = 0; mt < 4; mt++) {
                int row = aRowF + mt * 16;
                unsigned base = sA + row * 128;
                unsigned cH = ((unsigned)(ks * 2 + aKh)     ^ (row & 7)) << 4;
                unsigned cL = ((unsigned)(4 + ks * 2 + aKh) ^ (row & 7)) << 4;
                ldsm4(ah[mt], base + cH);
                ldsm4(al[mt], base + cL);
            }
#pragma unroll
            for (int nt = 0; nt < 4; nt++) {
                int k = ks * 16 + bKL;
                unsigned cc = ((unsigned)(bC + nt) ^ (k & 7)) << 4;
                ldsm2t(bh[nt], sBh + k * 256 + cc);
                ldsm2t(bl[nt], sBl + k * 256 + cc);
            }
#pragma unroll
            for (int mt = 0; mt < 4; mt++)
#pragma unroll
                for (int nt = 0; nt < 4; nt++) {
                    float* c = acc[mt * 4 + nt];
                    mma16816(c, ah[mt], bh[nt]);
                    mma16816(c, ah[mt], bl[nt]);
                    mma16816(c, al[mt], bh[nt]);
                }
        }
        __syncthreads();
    }

    // Epilogue. Fragment: c0,c1 -> row g, cols cp,cp+1; c2,c3 -> row g+8.
    const int g  = lane >> 2;
    const int cp = (lane & 3) << 1;
    if (SCATTER) {
        const int part = n0 >> 10;                    // tile within one of q/k/v
        float* dst = (part == 0) ? g_q : (part == 1) ? g_k : g_v;
#pragma unroll
        for (int mt = 0; mt < 4; mt++) {
#pragma unroll
            for (int nt = 0; nt < 4; nt++) {
                int n = n0 + nw * 32 + nt * 8 + cp;
                int c = n & (C_ - 1);
                int h = c >> 6, d = c & 63;
                float b0 = bias[n], b1 = bias[n + 1];
                float* a4 = acc[mt * 4 + nt];
#pragma unroll
                for (int rr = 0; rr < 2; rr++) {
                    int m  = m0 + mw * 64 + mt * 16 + g + rr * 8;
                    int bb = m >> 11, ss = m & (S_ - 1);
                    float2 o = make_float2(a4[rr * 2] + b0, a4[rr * 2 + 1] + b1);
                    *(float2*)&dst[(((size_t)(bb * H_ + h)) * S_ + ss) * D_ + d] = o;
                }
            }
        }
    } else {
#pragma unroll
        for (int mt = 0; mt < 4; mt++) {
#pragma unroll
            for (int nt = 0; nt < 4; nt++) {
                int n = n0 + nw * 32 + nt * 8 + cp;
                float b0 = bias[n], b1 = bias[n + 1];
                float* a4 = acc[mt * 4 + nt];
#pragma unroll
                for (int rr = 0; rr < 2; rr++) {
                    int m = m0 + mw * 64 + mt * 16 + g + rr * 8;
                    float2 o = make_float2(a4[rr * 2] + b0, a4[rr * 2 + 1] + b1);
                    *(float2*)&out[(size_t)m * C_ + n] = o;
                }
            }
        }
    }
}

// ---------------------------------------------------------------------------
// Flash attention (causal, fp32, online softmax) — unchanged from R2.
// ---------------------------------------------------------------------------
#define SIDX(x,y) (((x) << 6) | (((y) + (x)) & 63))

__global__ __launch_bounds__(256) void flash_attn()
{
    __shared__ float Qs [4096];
    __shared__ float KPs[4096];
    __shared__ float Vs [4096];

    const int tid = threadIdx.x;
    const int ty  = tid >> 4, tx = tid & 15;
    const int bh  = blockIdx.y;
    const int q0  = blockIdx.x << 6;

    const float* Qp = g_q + (size_t)bh * S_ * D_;
    const float* Kp = g_k + (size_t)bh * S_ * D_;
    const float* Vp = g_v + (size_t)bh * S_ * D_;

#pragma unroll
    for (int i = 0; i < 4; i++) {
        int f  = tid + (i << 8);
        int r  = f >> 4;
        int d4 = (f & 15) << 2;
        float4 qv = *(const float4*)(Qp + (size_t)(q0 + r) * D_ + d4);
        Qs[SIDX(d4+0, r)] = qv.x; Qs[SIDX(d4+1, r)] = qv.y;
        Qs[SIDX(d4+2, r)] = qv.z; Qs[SIDX(d4+3, r)] = qv.w;
    }

    float m_i[4], l_i[4], acc[4][4];
#pragma unroll
    for (int i = 0; i < 4; i++) {
        m_i[i] = -1e30f; l_i[i] = 0.f;
#pragma unroll
        for (int j = 0; j < 4; j++) acc[i][j] = 0.f;
    }

    const int ntiles = blockIdx.x + 1;
    const float scale = 0.125f;

    for (int t = 0; t < ntiles; t++) {
        const int k0 = t << 6;
#pragma unroll
        for (int i = 0; i < 4; i++) {
            int f  = tid + (i << 8);
            int r  = f >> 4;
            int d4 = (f & 15) << 2;
            float4 kv = *(const float4*)(Kp + (size_t)(k0 + r) * D_ + d4);
            KPs[SIDX(d4+0, r)] = kv.x; KPs[SIDX(d4+1, r)] = kv.y;
            KPs[SIDX(d4+2, r)] = kv.z; KPs[SIDX(d4+3, r)] = kv.w;
            float4 vv = *(const float4*)(Vp + (size_t)(k0 + r) * D_ + d4);
            Vs[SIDX(r, d4+0)] = vv.x; Vs[SIDX(r, d4+1)] = vv.y;
            Vs[SIDX(r, d4+2)] = vv.z; Vs[SIDX(r, d4+3)] = vv.w;
        }
        __syncthreads();

        float s[4][4];
#pragma unroll
        for (int i = 0; i < 4; i++)
#pragma unroll
            for (int j = 0; j < 4; j++) s[i][j] = 0.f;
        for (int d = 0; d < 64; d++) {
            float qf[4], kf[4];
#pragma unroll
            for (int c = 0; c < 4; c++) {
                qf[c] = Qs [SIDX(d, ty*4 + c)];
                kf[c] = KPs[SIDX(d, tx*4 + c)];
            }
#pragma unroll
            for (int i = 0; i < 4; i++)
#pragma unroll
                for (int j = 0; j < 4; j++)
                    s[i][j] = fmaf(qf[i], kf[j], s[i][j]);
        }

        const bool diag = (t == ntiles - 1);
#pragma unroll
        for (int i = 0; i < 4; i++)
#pragma unroll
            for (int j = 0; j < 4; j++) {
                float sv = s[i][j] * scale;
                if (diag && (k0 + tx*4 + j > q0 + ty*4 + i)) sv = -1e30f;
                s[i][j] = sv;
            }

        float p[4][4];
#pragma unroll
        for (int i = 0; i < 4; i++) {
            float v = fmaxf(fmaxf(s[i][0], s[i][1]), fmaxf(s[i][2], s[i][3]));
#pragma unroll
            for (int off = 8; off > 0; off >>= 1)
                v = fmaxf(v, __shfl_xor_sync(0xffffffffu, v, off, 16));
            float mn   = fmaxf(m_i[i], v);
            float corr = __expf(m_i[i] - mn);
            m_i[i] = mn;
            float rs = 0.f;
#pragma unroll
            for (int j = 0; j < 4; j++) {
                p[i][j] = __expf(s[i][j] - mn);
                rs += p[i][j];
            }
#pragma unroll
            for (int off = 8; off > 0; off >>= 1)
                rs += __shfl_xor_sync(0xffffffffu, rs, off, 16);
            l_i[i] = l_i[i] * corr + rs;
#pragma unroll
            for (int j = 0; j < 4; j++) acc[i][j] *= corr;
        }

        __syncthreads();
#pragma unroll
        for (int j = 0; j < 4; j++)
#pragma unroll
            for (int i = 0; i < 4; i++)
                KPs[SIDX(tx*4 + j, ty*4 + i)] = p[i][j];
        __syncthreads();

        for (int jj = 0; jj < 64; jj++) {
            float pf[4], vf[4];
#pragma unroll
            for (int c = 0; c < 4; c++) {
                pf[c] = KPs[SIDX(jj, ty*4 + c)];
                vf[c] = Vs [SIDX(jj, tx*4 + c)];
            }
#pragma unroll
            for (int i = 0; i < 4; i++)
#pragma unroll
                for (int j = 0; j < 4; j++)
                    acc[i][j] = fmaf(pf[i], vf[j], acc[i][j]);
        }
        __syncthreads();
    }

    const int bb = bh >> 4;
    const int h  = bh & 15;
#pragma unroll
    for (int i = 0; i < 4; i++) {
        float inv = 1.f / l_i[i];
        float4 o;
        o.x = acc[i][0] * inv; o.y = acc[i][1] * inv;
        o.z = acc[i][2] * inv; o.w = acc[i][3] * inv;
        *(float4*)(g_ao + ((size_t)bb * S_ + q0 + ty*4 + i) * C_
                         + h * D_ + tx*4) = o;
    }
}

// ---------------------------------------------------------------------------
extern "C" void kernel_launch(void* const* d_in, const int* in_sizes, int n_in,
                              void* d_out, int out_size)
{
    (void)in_sizes; (void)n_in; (void)out_size;
    const float* x      = (const float*)d_in[0];
    const float* W_attn = (const float*)d_in[1];
    const float* b_attn = (const float*)d_in[2];
    const float* W_proj = (const float*)d_in[3];
    const float* b_proj = (const float*)d_in[4];
    float* out = (float*)d_out;

    tc_gemm<N3_, true ><<<dim3(N3_/128, M_/128), 256>>>(x, W_attn, b_attn, nullptr);
    flash_attn<<<dim3(S_/64, B_*H_), 256>>>();
    tc_gemm<C_,  false><<<dim3(C_/128,  M_/128), 256>>>(nullptr, W_proj, b_proj, out);
}

// round 5
// speedup vs baseline: 3.4934x; 2.5155x over previous
#include <cuda_runtime.h>
#include <cuda_bf16.h>

#define B_  4
#define S_  2048
#define C_  1024
#define H_  16
#define D_  64
#define M_  (B_*S_)     // 8192
#define N3_ (3*C_)      // 3072

// Scratch (no allocations allowed): q/k/v as bf16 hi/lo pairs, [B,H,S,D]
__device__ __align__(16) __nv_bfloat16 g_qh[B_*H_*S_*D_];
__device__ __align__(16) __nv_bfloat16 g_ql[B_*H_*S_*D_];
__device__ __align__(16) __nv_bfloat16 g_kh[B_*H_*S_*D_];
__device__ __align__(16) __nv_bfloat16 g_kl[B_*H_*S_*D_];
__device__ __align__(16) __nv_bfloat16 g_vh[B_*H_*S_*D_];
__device__ __align__(16) __nv_bfloat16 g_vl[B_*H_*S_*D_];
__device__ float g_ao[M_*C_];   // attention output [B,S,C] fp32

// ---------------------------------------------------------------------------
// helpers
// ---------------------------------------------------------------------------
__device__ __forceinline__ unsigned pk2(float a, float b) {
    __nv_bfloat162 t = __floats2bfloat162_rn(a, b);
    return *reinterpret_cast<const unsigned*>(&t);
}
__device__ __forceinline__ float bfhi(float x) {
    return __bfloat162float(__float2bfloat16_rn(x));
}
__device__ __forceinline__ void ldsm4(unsigned r[4], unsigned addr) {
    asm volatile("ldmatrix.sync.aligned.m8n8.x4.shared.b16 {%0,%1,%2,%3}, [%4];\n"
        : "=r"(r[0]), "=r"(r[1]), "=r"(r[2]), "=r"(r[3]) : "r"(addr));
}
__device__ __forceinline__ void ldsm4t(unsigned r[4], unsigned addr) {
    asm volatile("ldmatrix.sync.aligned.m8n8.x4.trans.shared.b16 {%0,%1,%2,%3}, [%4];\n"
        : "=r"(r[0]), "=r"(r[1]), "=r"(r[2]), "=r"(r[3]) : "r"(addr));
}
__device__ __forceinline__ void ldsm2t(unsigned r[2], unsigned addr) {
    asm volatile("ldmatrix.sync.aligned.m8n8.x2.trans.shared.b16 {%0,%1}, [%2];\n"
        : "=r"(r[0]), "=r"(r[1]) : "r"(addr));
}
__device__ __forceinline__ void mma16816(float c[4], const unsigned a[4],
                                         const unsigned b[2]) {
    asm volatile(
        "mma.sync.aligned.m16n8k16.row.col.f32.bf16.bf16.f32 "
        "{%0,%1,%2,%3}, {%4,%5,%6,%7}, {%8,%9}, {%0,%1,%2,%3};\n"
        : "+f"(c[0]), "+f"(c[1]), "+f"(c[2]), "+f"(c[3])
        : "r"(a[0]), "r"(a[1]), "r"(a[2]), "r"(a[3]), "r"(b[0]), "r"(b[1]));
}

// ---------------------------------------------------------------------------
// Tensor-core GEMM with bf16 hi/lo split (3x MMA ~ fp32 accuracy).
// Block 128x128, BK=32, 256 threads (8 warps, 2m x 4n of 64x32 warp tiles).
// SCATTER=true: write bf16 hi/lo q/k/v [B,H,S,D] (q scaled by 1/8);
// else read g_ao and write fp32 out[m*C_+n].
// ---------------------------------------------------------------------------
template<int LDB, bool SCATTER>
__global__ __launch_bounds__(256) void tc_gemm(
    const float* __restrict__ Ain, const float* __restrict__ W,
    const float* __restrict__ bias, float* __restrict__ out)
{
    __shared__ __align__(16) unsigned char smem[32768];
    unsigned char* smemc = smem;
    const unsigned sA  = (unsigned)__cvta_generic_to_shared(smem);
    const unsigned sBh = sA + 16384;
    const unsigned sBl = sA + 24576;

    const float* __restrict__ A = SCATTER ? Ain : (const float*)g_ao;

    const int tid  = threadIdx.x;
    const int lane = tid & 31, warp = tid >> 5;
    const int mw = warp & 1, nw = warp >> 1;
    const int m0 = blockIdx.y << 7, n0 = blockIdx.x << 7;

    const float* aPtr[4]; const float* bPtr[4];
    unsigned aOffH[4], aOffL[4], bOff[4];
#pragma unroll
    for (int i = 0; i < 4; i++) {
        int f = i * 256 + tid;
        int ar = f >> 3, akq = (f & 7) << 2;
        aPtr[i] = A + (size_t)(m0 + ar) * C_ + akq;
        aOffH[i] = ar * 128 + ((( (akq >> 3))     ^ (ar & 7)) << 4) + ((akq & 7) << 1);
        aOffL[i] = ar * 128 + (((4 + (akq >> 3))  ^ (ar & 7)) << 4) + ((akq & 7) << 1);
        int bk = f >> 5, bnq = (f & 31) << 2;
        bPtr[i] = W + (size_t)bk * LDB + n0 + bnq;
        bOff[i] = bk * 256 + (((bnq >> 3) ^ (bk & 7)) << 4) + ((bnq & 7) << 1);
    }

    float acc[16][4];
#pragma unroll
    for (int i = 0; i < 16; i++)
#pragma unroll
        for (int j = 0; j < 4; j++) acc[i][j] = 0.f;

    const int aRowF = mw * 64 + (lane & 15);
    const int aKh   = lane >> 4;
    const int bKL   = lane & 15;
    const int bC    = nw * 4;

    float4 pa[4], pb[4];
#pragma unroll
    for (int i = 0; i < 4; i++) { pa[i] = *(const float4*)aPtr[i];
                                  pb[i] = *(const float4*)bPtr[i]; }

    for (int kt = 0; kt < C_ / 32; kt++) {
#pragma unroll
        for (int i = 0; i < 4; i++) {
            float h0 = bfhi(pa[i].x), h1 = bfhi(pa[i].y);
            float h2 = bfhi(pa[i].z), h3 = bfhi(pa[i].w);
            *(uint2*)(smemc + aOffH[i]) = make_uint2(pk2(h0, h1), pk2(h2, h3));
            *(uint2*)(smemc + aOffL[i]) = make_uint2(
                pk2(pa[i].x - h0, pa[i].y - h1), pk2(pa[i].z - h2, pa[i].w - h3));
            float g0 = bfhi(pb[i].x), g1 = bfhi(pb[i].y);
            float g2 = bfhi(pb[i].z), g3 = bfhi(pb[i].w);
            *(uint2*)(smemc + 16384 + bOff[i]) = make_uint2(pk2(g0, g1), pk2(g2, g3));
            *(uint2*)(smemc + 24576 + bOff[i]) = make_uint2(
                pk2(pb[i].x - g0, pb[i].y - g1), pk2(pb[i].z - g2, pb[i].w - g3));
        }
        __syncthreads();

        if (kt + 1 < C_ / 32) {
#pragma unroll
            for (int i = 0; i < 4; i++) {
                aPtr[i] += 32;
                bPtr[i] += (size_t)32 * LDB;
                pa[i] = *(const float4*)aPtr[i];
                pb[i] = *(const float4*)bPtr[i];
            }
        }

#pragma unroll
        for (int ks = 0; ks < 2; ks++) {
            unsigned ah[4][4], al[4][4], bh[4][2], bl[4][2];
#pragma unroll
            for (int mt = 0; mt < 4; mt++) {
                int row = aRowF + mt * 16;
                unsigned base = sA + row * 128;
                unsigned cH = ((unsigned)(ks * 2 + aKh)     ^ (row & 7)) << 4;
                unsigned cL = ((unsigned)(4 + ks * 2 + aKh) ^ (row & 7)) << 4;
                ldsm4(ah[mt], base + cH);
                ldsm4(al[mt], base + cL);
            }
#pragma unroll
            for (int nt = 0; nt < 4; nt++) {
                int k = ks * 16 + bKL;
                unsigned cc = ((unsigned)(bC + nt) ^ (k & 7)) << 4;
                ldsm2t(bh[nt], sBh + k * 256 + cc);
                ldsm2t(bl[nt], sBl + k * 256 + cc);
            }
#pragma unroll
            for (int mt = 0; mt < 4; mt++)
#pragma unroll
                for (int nt = 0; nt < 4; nt++) {
                    float* c = acc[mt * 4 + nt];
                    mma16816(c, ah[mt], bh[nt]);
                    mma16816(c, ah[mt], bl[nt]);
                    mma16816(c, al[mt], bh[nt]);
                }
        }
        __syncthreads();
    }

    const int g  = lane >> 2;
    const int cp = (lane & 3) << 1;
    if (SCATTER) {
        const int part = n0 >> 10;
        __nv_bfloat16* dH = (part == 0) ? g_qh : (part == 1) ? g_kh : g_vh;
        __nv_bfloat16* dL = (part == 0) ? g_ql : (part == 1) ? g_kl : g_vl;
        const float fs = (part == 0) ? 0.125f : 1.0f;   // fold 1/sqrt(D) into q
#pragma unroll
        for (int mt = 0; mt < 4; mt++) {
#pragma unroll
            for (int nt = 0; nt < 4; nt++) {
                int n = n0 + nw * 32 + nt * 8 + cp;
                int c = n & (C_ - 1);
                int hh = c >> 6, d = c & 63;
                float b0 = bias[n], b1 = bias[n + 1];
                float* a4 = acc[mt * 4 + nt];
#pragma unroll
                for (int rr = 0; rr < 2; rr++) {
                    int m  = m0 + mw * 64 + mt * 16 + g + rr * 8;
                    int bb = m >> 11, ss = m & (S_ - 1);
                    float v0 = (a4[rr * 2] + b0) * fs;
                    float v1 = (a4[rr * 2 + 1] + b1) * fs;
                    float h0 = bfhi(v0), h1 = bfhi(v1);
                    size_t idx = (((size_t)(bb * H_ + hh)) * S_ + ss) * D_ + d;
                    *(unsigned*)&dH[idx] = pk2(v0, v1);
                    *(unsigned*)&dL[idx] = pk2(v0 - h0, v1 - h1);
                }
            }
        }
    } else {
#pragma unroll
        for (int mt = 0; mt < 4; mt++) {
#pragma unroll
            for (int nt = 0; nt < 4; nt++) {
                int n = n0 + nw * 32 + nt * 8 + cp;
                float b0 = bias[n], b1 = bias[n + 1];
                float* a4 = acc[mt * 4 + nt];
#pragma unroll
                for (int rr = 0; rr < 2; rr++) {
                    int m = m0 + mw * 64 + mt * 16 + g + rr * 8;
                    float2 o = make_float2(a4[rr * 2] + b0, a4[rr * 2 + 1] + b1);
                    *(float2*)&out[(size_t)m * C_ + n] = o;
                }
            }
        }
    }
}

// ---------------------------------------------------------------------------
// Tensor-core flash attention (causal, online softmax, bf16 hi/lo split).
// Block: 128 threads (4 warps), 64 queries (16/warp), 64-key tiles, D=64.
// SMEM 48KB: Qh/Ql/Kh/Kl/Vh/Vl, each 64 rows x 128B, XOR-swizzled.
// S-frag (m16n8 C) pairs reused directly as P A-frags (m16k16) for PV.
// ---------------------------------------------------------------------------
__global__ __launch_bounds__(128) void flash_attn_tc()
{
    __shared__ __align__(16) unsigned char sm[49152];
    const unsigned sb  = (unsigned)__cvta_generic_to_shared(sm);
    const unsigned sQh = sb,          sQl = sb + 8192;
    const unsigned sKh = sb + 16384,  sKl = sb + 24576;
    const unsigned sVh = sb + 32768,  sVl = sb + 40960;

    const int tid  = threadIdx.x;
    const int lane = tid & 31, warp = tid >> 5;
    const int bh = blockIdx.y;
    const int q0 = blockIdx.x << 6;
    const size_t base = (size_t)bh * (S_ * D_);
    const int g = lane >> 2, t4 = lane & 3;

    // Load Q tile (hi/lo bf16, already scaled by 1/8)
#pragma unroll
    for (int i = 0; i < 4; i++) {
        int f = i * 128 + tid;
        int r = f >> 3, ch = f & 7;
        unsigned off = r * 128 + (((unsigned)(ch ^ (r & 7))) << 4);
        size_t src = base + (size_t)(q0 + r) * 64 + ch * 8;
        *(uint4*)(sm + off)        = *(const uint4*)(g_qh + src);
        *(uint4*)(sm + 8192 + off) = *(const uint4*)(g_ql + src);
    }

    float o[8][4];
#pragma unroll
    for (int i = 0; i < 8; i++)
#pragma unroll
        for (int j = 0; j < 4; j++) o[i][j] = 0.f;
    float mr[2] = {-1e30f, -1e30f}, lr[2] = {0.f, 0.f};

    const int ntiles = blockIdx.x + 1;
    for (int t = 0; t < ntiles; t++) {
        const int k0 = t << 6;
        __syncthreads();   // protect prev-iter K/V reads (and Q stores on iter 0)
#pragma unroll
        for (int i = 0; i < 4; i++) {
            int f = i * 128 + tid;
            int r = f >> 3, ch = f & 7;
            unsigned off = r * 128 + (((unsigned)(ch ^ (r & 7))) << 4);
            size_t src = base + (size_t)(k0 + r) * 64 + ch * 8;
            *(uint4*)(sm + 16384 + off) = *(const uint4*)(g_kh + src);
            *(uint4*)(sm + 24576 + off) = *(const uint4*)(g_kl + src);
            *(uint4*)(sm + 32768 + off) = *(const uint4*)(g_vh + src);
            *(uint4*)(sm + 40960 + off) = *(const uint4*)(g_vl + src);
        }
        __syncthreads();

        // ---- S = Q @ K^T (hi/lo split: 3 MMAs) ----
        float s[8][4];
#pragma unroll
        for (int i = 0; i < 8; i++)
#pragma unroll
            for (int j = 0; j < 4; j++) s[i][j] = 0.f;

#pragma unroll
        for (int kc = 0; kc < 4; kc++) {
            unsigned ah[4], al[4];
            int qr = warp * 16 + (lane & 15);
            unsigned qoff = qr * 128 +
                (((unsigned)((2 * kc + (lane >> 4)) ^ (qr & 7))) << 4);
            ldsm4(ah, sQh + qoff);
            ldsm4(al, sQl + qoff);
#pragma unroll
            for (int ntp = 0; ntp < 4; ntp++) {
                unsigned kbh[4], kbl[4];
                int kr = ntp * 16 + ((lane >> 4) << 3) + (lane & 7);
                unsigned koff = kr * 128 +
                    (((unsigned)((2 * kc + ((lane >> 3) & 1)) ^ (kr & 7))) << 4);
                ldsm4(kbh, sKh + koff);
                ldsm4(kbl, sKl + koff);
                mma16816(s[2*ntp],   ah, kbh);
                mma16816(s[2*ntp],   ah, kbl);
                mma16816(s[2*ntp],   al, kbh);
                mma16816(s[2*ntp+1], ah, kbh + 2);
                mma16816(s[2*ntp+1], ah, kbl + 2);
                mma16816(s[2*ntp+1], al, kbh + 2);
            }
        }

        // ---- causal mask (diagonal tile only; q0 == k0 there) ----
        if (t == ntiles - 1) {
            int row_lo = warp * 16 + g;
            int row_hi = row_lo + 8;
#pragma unroll
            for (int nt = 0; nt < 8; nt++) {
#pragma unroll
                for (int j = 0; j < 2; j++) {
                    int col = nt * 8 + 2 * t4 + j;
                    if (col > row_lo) s[nt][j]     = -1e30f;
                    if (col > row_hi) s[nt][2 + j] = -1e30f;
                }
            }
        }

        // ---- online softmax (rows g and g+8; reduce across t4 group) ----
#pragma unroll
        for (int hf = 0; hf < 2; hf++) {
            float mx = -1e30f;
#pragma unroll
            for (int nt = 0; nt < 8; nt++)
                mx = fmaxf(mx, fmaxf(s[nt][2*hf], s[nt][2*hf+1]));
            mx = fmaxf(mx, __shfl_xor_sync(0xffffffffu, mx, 1));
            mx = fmaxf(mx, __shfl_xor_sync(0xffffffffu, mx, 2));
            float mn   = fmaxf(mr[hf], mx);
            float corr = __expf(mr[hf] - mn);
            mr[hf] = mn;
            float rs = 0.f;
#pragma unroll
            for (int nt = 0; nt < 8; nt++) {
                float p0 = __expf(s[nt][2*hf]     - mn);
                float p1 = __expf(s[nt][2*hf + 1] - mn);
                s[nt][2*hf] = p0; s[nt][2*hf+1] = p1;
                rs += p0 + p1;
            }
            rs += __shfl_xor_sync(0xffffffffu, rs, 1);
            rs += __shfl_xor_sync(0xffffffffu, rs, 2);
            lr[hf] = lr[hf] * corr + rs;
#pragma unroll
            for (int dt = 0; dt < 8; dt++) {
                o[dt][2*hf]     *= corr;
                o[dt][2*hf + 1] *= corr;
            }
        }

        // ---- O += P @ V (P from S-frags in registers, hi/lo split) ----
#pragma unroll
        for (int kc = 0; kc < 4; kc++) {
            unsigned pah[4], pal[4];
#pragma unroll
            for (int q = 0; q < 2; q++) {
                float x0 = s[2*kc + q][0], x1 = s[2*kc + q][1];
                float x2 = s[2*kc + q][2], x3 = s[2*kc + q][3];
                float h0 = bfhi(x0), h1 = bfhi(x1);
                float h2 = bfhi(x2), h3 = bfhi(x3);
                pah[2*q]     = pk2(x0, x1);
                pah[2*q + 1] = pk2(x2, x3);
                pal[2*q]     = pk2(x0 - h0, x1 - h1);
                pal[2*q + 1] = pk2(x2 - h2, x3 - h3);
            }
#pragma unroll
            for (int dtp = 0; dtp < 4; dtp++) {
                unsigned vbh[4], vbl[4];
                int vr = kc * 16 + (lane & 15);
                unsigned voff = vr * 128 +
                    (((unsigned)((2 * dtp + (lane >> 4)) ^ (vr & 7))) << 4);
                ldsm4t(vbh, sVh + voff);
                ldsm4t(vbl, sVl + voff);
                mma16816(o[2*dtp],   pah, vbh);
                mma16816(o[2*dtp],   pah, vbl);
                mma16816(o[2*dtp],   pal, vbh);
                mma16816(o[2*dtp+1], pah, vbh + 2);
                mma16816(o[2*dtp+1], pah, vbl + 2);
                mma16816(o[2*dtp+1], pal, vbh + 2);
            }
        }
    }

    // ---- epilogue: normalize, write fp32 to g_ao[B,S,C] ----
    const int bb = bh >> 4, h = bh & 15;
    const float inv0 = 1.f / lr[0], inv1 = 1.f / lr[1];
    const int mrow0 = q0 + warp * 16 + g;
#pragma unroll
    for (int dt = 0; dt < 8; dt++) {
        int col = h * 64 + dt * 8 + 2 * t4;
        float2 v0 = make_float2(o[dt][0] * inv0, o[dt][1] * inv0);
        float2 v1 = make_float2(o[dt][2] * inv1, o[dt][3] * inv1);
        *(float2*)&g_ao[((size_t)bb * S_ + mrow0)     * C_ + col] = v0;
        *(float2*)&g_ao[((size_t)bb * S_ + mrow0 + 8) * C_ + col] = v1;
    }
}

// ---------------------------------------------------------------------------
extern "C" void kernel_launch(void* const* d_in, const int* in_sizes, int n_in,
                              void* d_out, int out_size)
{
    (void)in_sizes; (void)n_in; (void)out_size;
    const float* x      = (const float*)d_in[0];
    const float* W_attn = (const float*)d_in[1];
    const float* b_attn = (const float*)d_in[2];
    const float* W_proj = (const float*)d_in[3];
    const float* b_proj = (const float*)d_in[4];
    float* out = (float*)d_out;

    tc_gemm<N3_, true ><<<dim3(N3_/128, M_/128), 256>>>(x, W_attn, b_attn, nullptr);
    flash_attn_tc<<<dim3(S_/64, B_*H_), 128>>>();
    tc_gemm<C_,  false><<<dim3(C_/128,  M_/128), 256>>>(nullptr, W_proj, b_proj, out);
}

// round 6
// speedup vs baseline: 3.7124x; 1.0627x over previous
#include <cuda_runtime.h>
#include <cuda_bf16.h>

#define B_  4
#define S_  2048
#define C_  1024
#define H_  16
#define D_  64
#define M_  (B_*S_)     // 8192
#define N3_ (3*C_)      // 3072

// Scratch (no allocations allowed)
__device__ __align__(16) __nv_bfloat16 g_qh[B_*H_*S_*D_];
__device__ __align__(16) __nv_bfloat16 g_ql[B_*H_*S_*D_];
__device__ __align__(16) __nv_bfloat16 g_kh[B_*H_*S_*D_];
__device__ __align__(16) __nv_bfloat16 g_kl[B_*H_*S_*D_];
__device__ __align__(16) __nv_bfloat16 g_vh[B_*H_*S_*D_];
__device__ __align__(16) __nv_bfloat16 g_vl[B_*H_*S_*D_];
// A operands in segmented layout: per row, per 16-k group: [16 hi | 16 lo] bf16
__device__ __align__(16) __nv_bfloat16 g_xa [M_*C_*2];   // converted x
__device__ __align__(16) __nv_bfloat16 g_aoa[M_*C_*2];   // attention output
// Weight planes (row-major [K][N])
__device__ __align__(16) __nv_bfloat16 g_wah[C_*N3_], g_wal[C_*N3_];
__device__ __align__(16) __nv_bfloat16 g_wph[C_*C_],  g_wpl[C_*C_];

// ---------------------------------------------------------------------------
// helpers
// ---------------------------------------------------------------------------
__device__ __forceinline__ unsigned pk2(float a, float b) {
    __nv_bfloat162 t = __floats2bfloat162_rn(a, b);
    return *reinterpret_cast<const unsigned*>(&t);
}
__device__ __forceinline__ float bfhi(float x) {
    return __bfloat162float(__float2bfloat16_rn(x));
}
__device__ __forceinline__ void ldsm4(unsigned r[4], unsigned addr) {
    asm volatile("ldmatrix.sync.aligned.m8n8.x4.shared.b16 {%0,%1,%2,%3}, [%4];\n"
        : "=r"(r[0]), "=r"(r[1]), "=r"(r[2]), "=r"(r[3]) : "r"(addr));
}
__device__ __forceinline__ void ldsm4t(unsigned r[4], unsigned addr) {
    asm volatile("ldmatrix.sync.aligned.m8n8.x4.trans.shared.b16 {%0,%1,%2,%3}, [%4];\n"
        : "=r"(r[0]), "=r"(r[1]), "=r"(r[2]), "=r"(r[3]) : "r"(addr));
}
__device__ __forceinline__ void mma16816(float c[4], const unsigned a[4],
                                         const unsigned b[2]) {
    asm volatile(
        "mma.sync.aligned.m16n8k16.row.col.f32.bf16.bf16.f32 "
        "{%0,%1,%2,%3}, {%4,%5,%6,%7}, {%8,%9}, {%0,%1,%2,%3};\n"
        : "+f"(c[0]), "+f"(c[1]), "+f"(c[2]), "+f"(c[3])
        : "r"(a[0]), "r"(a[1]), "r"(a[2]), "r"(a[3]), "r"(b[0]), "r"(b[1]));
}
__device__ __forceinline__ void cpa16(unsigned dst, const void* src) {
    asm volatile("cp.async.cg.shared.global [%0], [%1], 16;\n"
        :: "r"(dst), "l"(__cvta_generic_to_global(src)));
}
#define CP_COMMIT() asm volatile("cp.async.commit_group;\n" ::: "memory")
#define CP_WAIT1()  asm volatile("cp.async.wait_group 1;\n" ::: "memory")

// ---------------------------------------------------------------------------
// Conversion kernels (memory-bound, run once)
// ---------------------------------------------------------------------------
__global__ __launch_bounds__(256) void conv_seg_x(const float* __restrict__ src)
{
    size_t s = (size_t)blockIdx.x * 256 + threadIdx.x;   // 16-elem segment id
    const float4* p = (const float4*)(src + s * 16);
    float4 a = p[0], b = p[1], c = p[2], d = p[3];
    __nv_bfloat16* dst = g_xa + s * 32;
    uint4 u;
    u.x = pk2(a.x, a.y); u.y = pk2(a.z, a.w);
    u.z = pk2(b.x, b.y); u.w = pk2(b.z, b.w);
    *(uint4*)dst = u;
    u.x = pk2(c.x, c.y); u.y = pk2(c.z, c.w);
    u.z = pk2(d.x, d.y); u.w = pk2(d.z, d.w);
    *(uint4*)(dst + 8) = u;
    u.x = pk2(a.x - bfhi(a.x), a.y - bfhi(a.y));
    u.y = pk2(a.z - bfhi(a.z), a.w - bfhi(a.w));
    u.z = pk2(b.x - bfhi(b.x), b.y - bfhi(b.y));
    u.w = pk2(b.z - bfhi(b.z), b.w - bfhi(b.w));
    *(uint4*)(dst + 16) = u;
    u.x = pk2(c.x - bfhi(c.x), c.y - bfhi(c.y));
    u.y = pk2(c.z - bfhi(c.z), c.w - bfhi(c.w));
    u.z = pk2(d.x - bfhi(d.x), d.y - bfhi(d.y));
    u.w = pk2(d.z - bfhi(d.z), d.w - bfhi(d.w));
    *(uint4*)(dst + 24) = u;
}

template<int P>   // 0 = W_attn, 1 = W_proj
__global__ __launch_bounds__(256) void conv_plane(const float* __restrict__ src)
{
    size_t i = ((size_t)blockIdx.x * 256 + threadIdx.x) * 8;
    const float4* p = (const float4*)(src + i);
    float4 a = p[0], b = p[1];
    __nv_bfloat16* dh = (P == 0) ? g_wah : g_wph;
    __nv_bfloat16* dl = (P == 0) ? g_wal : g_wpl;
    uint4 u;
    u.x = pk2(a.x, a.y); u.y = pk2(a.z, a.w);
    u.z = pk2(b.x, b.y); u.w = pk2(b.z, b.w);
    *(uint4*)(dh + i) = u;
    u.x = pk2(a.x - bfhi(a.x), a.y - bfhi(a.y));
    u.y = pk2(a.z - bfhi(a.z), a.w - bfhi(a.w));
    u.z = pk2(b.x - bfhi(b.x), b.y - bfhi(b.y));
    u.w = pk2(b.z - bfhi(b.z), b.w - bfhi(b.w));
    *(uint4*)(dl + i) = u;
}

// ---------------------------------------------------------------------------
// Tensor-core GEMM, pre-converted bf16 hi/lo operands, 3-stage cp.async.
// Block 128x128, BK=16, 256 threads (8 warps, 2m x 4n of 64x32 warp tiles).
// Stage smem 16KB (A 8KB packed 64x128B, Bh 4KB, Bl 4KB) x 3 = 48KB.
// SCATTER=true: A=g_xa, W=wa planes, write bf16 hi/lo q/k/v (q scaled 1/8).
// SCATTER=false: A=g_aoa, W=wp planes, write fp32 out.
// ---------------------------------------------------------------------------
template<int LDB, bool SCATTER>
__global__ __launch_bounds__(256) void tc_gemm2(
    const float* __restrict__ bias, float* __restrict__ out)
{
    __shared__ __align__(16) unsigned char smem[49152];
    const unsigned sb = (unsigned)__cvta_generic_to_shared(smem);
    const __nv_bfloat16* Aseg = SCATTER ? g_xa  : g_aoa;
    const __nv_bfloat16* Whp  = SCATTER ? g_wah : g_wph;
    const __nv_bfloat16* Wlp  = SCATTER ? g_wal : g_wpl;

    const int tid = threadIdx.x, lane = tid & 31, warp = tid >> 5;
    const int mw = warp & 1, nw = warp >> 1;
    const int m0 = blockIdx.y << 7, n0 = blockIdx.x << 7;

    // copy descriptors: 2 A-chunks + 2 B-chunks (16B) per thread per stage
    const char* aSrc[2]; unsigned aDst[2];
#pragma unroll
    for (int i = 0; i < 2; i++) {
        int f = i * 256 + tid;               // 0..511
        int row = f >> 2, c = f & 3;
        aSrc[i] = (const char*)Aseg + (size_t)(m0 + row) * 4096 + c * 16;
        int p = row >> 1, s5 = row & 1;
        aDst[i] = p * 128 + ((((s5 << 2) | c) ^ (p & 7)) << 4);
    }
    const char* bSrc[2]; unsigned bDst[2];
#pragma unroll
    for (int i = 0; i < 2; i++) {
        int f = i * 256 + tid;               // 0..511
        int k = f >> 5, ch = f & 31;
        int ishi = (ch < 16), nc = ch & 15;
        const __nv_bfloat16* plane = ishi ? Whp : Wlp;
        bSrc[i] = (const char*)plane + ((size_t)k * LDB + n0 + nc * 8) * 2;
        bDst[i] = 8192 + (ishi ? 0 : 4096) + k * 256 + ((nc ^ (k & 7)) << 4);
    }
    const size_t bStep = (size_t)16 * LDB * 2;

    float acc[16][4];
#pragma unroll
    for (int i = 0; i < 16; i++)
#pragma unroll
        for (int j = 0; j < 4; j++) acc[i][j] = 0.f;

    auto issue = [&](int kt) {
        unsigned st = sb + (kt % 3) * 16384;
#pragma unroll
        for (int i = 0; i < 2; i++)
            cpa16(st + aDst[i], aSrc[i] + (size_t)kt * 64);
#pragma unroll
        for (int i = 0; i < 2; i++)
            cpa16(st + bDst[i], bSrc[i] + (size_t)kt * bStep);
    };

    issue(0); CP_COMMIT();
    issue(1); CP_COMMIT();

    const int KT = C_ / 16;   // 64
    for (int kt = 0; kt < KT; kt++) {
        CP_WAIT1();
        __syncthreads();      // stage kt ready; all warps done with stage kt-1
        if (kt + 2 < KT) issue(kt + 2);
        CP_COMMIT();

        const unsigned sA  = sb + (kt % 3) * 16384;
        const unsigned sBh = sA + 8192, sBl = sA + 12288;

        unsigned ah[4][4], al[4][4];
#pragma unroll
        for (int mt = 0; mt < 4; mt++) {
            int row = mw * 64 + mt * 16 + (lane & 15);
            int p = row >> 1, s5 = row & 1;
            int c = lane >> 4;
            unsigned b128 = sA + p * 128;
            ldsm4(ah[mt], b128 + ((((s5 << 2) | c)       ^ (p & 7)) << 4));
            ldsm4(al[mt], b128 + ((((s5 << 2) | (2 + c)) ^ (p & 7)) << 4));
        }
        unsigned bh[2][4], bl[2][4];
#pragma unroll
        for (int tp = 0; tp < 2; tp++) {
            int k  = lane & 15;
            int nc = nw * 4 + tp * 2 + (lane >> 4);
            unsigned off = k * 256 + ((nc ^ (k & 7)) << 4);
            ldsm4t(bh[tp], sBh + off);
            ldsm4t(bl[tp], sBl + off);
        }
#pragma unroll
        for (int mt = 0; mt < 4; mt++)
#pragma unroll
            for (int tp = 0; tp < 2; tp++)
#pragma unroll
                for (int hf = 0; hf < 2; hf++) {
                    float* c = acc[mt * 4 + tp * 2 + hf];
                    const unsigned* BH = bh[tp] + hf * 2;
                    const unsigned* BL = bl[tp] + hf * 2;
                    mma16816(c, ah[mt], BH);
                    mma16816(c, ah[mt], BL);
                    mma16816(c, al[mt], BH);
                }
    }

    // Epilogue. Fragment: c0,c1 -> row g, cols cp..; c2,c3 -> row g+8.
    const int g  = lane >> 2;
    const int cp = (lane & 3) << 1;
    if (SCATTER) {
        const int part = n0 >> 10;
        __nv_bfloat16* dH = (part == 0) ? g_qh : (part == 1) ? g_kh : g_vh;
        __nv_bfloat16* dL = (part == 0) ? g_ql : (part == 1) ? g_kl : g_vl;
        const float fs = (part == 0) ? 0.125f : 1.0f;   // fold 1/sqrt(D) into q
#pragma unroll
        for (int mt = 0; mt < 4; mt++) {
#pragma unroll
            for (int nt = 0; nt < 4; nt++) {
                int n = n0 + nw * 32 + nt * 8 + cp;
                int c = n & (C_ - 1);
                int hh = c >> 6, d = c & 63;
                float b0 = bias[n], b1 = bias[n + 1];
                float* a4 = acc[mt * 4 + nt];
#pragma unroll
                for (int rr = 0; rr < 2; rr++) {
                    int m  = m0 + mw * 64 + mt * 16 + g + rr * 8;
                    int bb = m >> 11, ss = m & (S_ - 1);
                    float v0 = (a4[rr * 2] + b0) * fs;
                    float v1 = (a4[rr * 2 + 1] + b1) * fs;
                    float h0 = bfhi(v0), h1 = bfhi(v1);
                    size_t idx = (((size_t)(bb * H_ + hh)) * S_ + ss) * D_ + d;
                    *(unsigned*)&dH[idx] = pk2(v0, v1);
                    *(unsigned*)&dL[idx] = pk2(v0 - h0, v1 - h1);
                }
            }
        }
    } else {
#pragma unroll
        for (int mt = 0; mt < 4; mt++) {
#pragma unroll
            for (int nt = 0; nt < 4; nt++) {
                int n = n0 + nw * 32 + nt * 8 + cp;
                float b0 = bias[n], b1 = bias[n + 1];
                float* a4 = acc[mt * 4 + nt];
#pragma unroll
                for (int rr = 0; rr < 2; rr++) {
                    int m = m0 + mw * 64 + mt * 16 + g + rr * 8;
                    float2 o = make_float2(a4[rr * 2] + b0, a4[rr * 2 + 1] + b1);
                    *(float2*)&out[(size_t)m * C_ + n] = o;
                }
            }
        }
    }
}

// ---------------------------------------------------------------------------
// Tensor-core flash attention (causal, online softmax, bf16 hi/lo split).
// Block: 128 threads (4 warps), 64 queries, 64-key tiles, D=64.
// Epilogue now writes segmented bf16 hi/lo layout for GEMM2 (g_aoa).
// ---------------------------------------------------------------------------
__global__ __launch_bounds__(128) void flash_attn_tc()
{
    __shared__ __align__(16) unsigned char sm[49152];
    const unsigned sb  = (unsigned)__cvta_generic_to_shared(sm);
    const unsigned sQh = sb,          sQl = sb + 8192;
    const unsigned sKh = sb + 16384,  sKl = sb + 24576;
    const unsigned sVh = sb + 32768,  sVl = sb + 40960;

    const int tid  = threadIdx.x;
    const int lane = tid & 31, warp = tid >> 5;
    const int bh = blockIdx.y;
    const int q0 = blockIdx.x << 6;
    const size_t base = (size_t)bh * (S_ * D_);
    const int g = lane >> 2, t4 = lane & 3;

#pragma unroll
    for (int i = 0; i < 4; i++) {
        int f = i * 128 + tid;
        int r = f >> 3, ch = f & 7;
        unsigned off = r * 128 + (((unsigned)(ch ^ (r & 7))) << 4);
        size_t src = base + (size_t)(q0 + r) * 64 + ch * 8;
        *(uint4*)(sm + off)        = *(const uint4*)(g_qh + src);
        *(uint4*)(sm + 8192 + off) = *(const uint4*)(g_ql + src);
    }

    float o[8][4];
#pragma unroll
    for (int i = 0; i < 8; i++)
#pragma unroll
        for (int j = 0; j < 4; j++) o[i][j] = 0.f;
    float mr[2] = {-1e30f, -1e30f}, lr[2] = {0.f, 0.f};

    const int ntiles = blockIdx.x + 1;
    for (int t = 0; t < ntiles; t++) {
        const int k0 = t << 6;
        __syncthreads();
#pragma unroll
        for (int i = 0; i < 4; i++) {
            int f = i * 128 + tid;
            int r = f >> 3, ch = f & 7;
            unsigned off = r * 128 + (((unsigned)(ch ^ (r & 7))) << 4);
            size_t src = base + (size_t)(k0 + r) * 64 + ch * 8;
            *(uint4*)(sm + 16384 + off) = *(const uint4*)(g_kh + src);
            *(uint4*)(sm + 24576 + off) = *(const uint4*)(g_kl + src);
            *(uint4*)(sm + 32768 + off) = *(const uint4*)(g_vh + src);
            *(uint4*)(sm + 40960 + off) = *(const uint4*)(g_vl + src);
        }
        __syncthreads();

        float s[8][4];
#pragma unroll
        for (int i = 0; i < 8; i++)
#pragma unroll
            for (int j = 0; j < 4; j++) s[i][j] = 0.f;

#pragma unroll
        for (int kc = 0; kc < 4; kc++) {
            unsigned ah[4], al[4];
            int qr = warp * 16 + (lane & 15);
            unsigned qoff = qr * 128 +
                (((unsigned)((2 * kc + (lane >> 4)) ^ (qr & 7))) << 4);
            ldsm4(ah, sQh + qoff);
            ldsm4(al, sQl + qoff);
#pragma unroll
            for (int ntp = 0; ntp < 4; ntp++) {
                unsigned kbh[4], kbl[4];
                int kr = ntp * 16 + ((lane >> 4) << 3) + (lane & 7);
                unsigned koff = kr * 128 +
                    (((unsigned)((2 * kc + ((lane >> 3) & 1)) ^ (kr & 7))) << 4);
                ldsm4(kbh, sKh + koff);
                ldsm4(kbl, sKl + koff);
                mma16816(s[2*ntp],   ah, kbh);
                mma16816(s[2*ntp],   ah, kbl);
                mma16816(s[2*ntp],   al, kbh);
                mma16816(s[2*ntp+1], ah, kbh + 2);
                mma16816(s[2*ntp+1], ah, kbl + 2);
                mma16816(s[2*ntp+1], al, kbh + 2);
            }
        }

        if (t == ntiles - 1) {
            int row_lo = warp * 16 + g;
            int row_hi = row_lo + 8;
#pragma unroll
            for (int nt = 0; nt < 8; nt++) {
#pragma unroll
                for (int j = 0; j < 2; j++) {
                    int col = nt * 8 + 2 * t4 + j;
                    if (col > row_lo) s[nt][j]     = -1e30f;
                    if (col > row_hi) s[nt][2 + j] = -1e30f;
                }
            }
        }

#pragma unroll
        for (int hf = 0; hf < 2; hf++) {
            float mx = -1e30f;
#pragma unroll
            for (int nt = 0; nt < 8; nt++)
                mx = fmaxf(mx, fmaxf(s[nt][2*hf], s[nt][2*hf+1]));
            mx = fmaxf(mx, __shfl_xor_sync(0xffffffffu, mx, 1));
            mx = fmaxf(mx, __shfl_xor_sync(0xffffffffu, mx, 2));
            float mn   = fmaxf(mr[hf], mx);
            float corr = __expf(mr[hf] - mn);
            mr[hf] = mn;
            float rs = 0.f;
#pragma unroll
            for (int nt = 0; nt < 8; nt++) {
                float p0 = __expf(s[nt][2*hf]     - mn);
                float p1 = __expf(s[nt][2*hf + 1] - mn);
                s[nt][2*hf] = p0; s[nt][2*hf+1] = p1;
                rs += p0 + p1;
            }
            rs += __shfl_xor_sync(0xffffffffu, rs, 1);
            rs += __shfl_xor_sync(0xffffffffu, rs, 2);
            lr[hf] = lr[hf] * corr + rs;
#pragma unroll
            for (int dt = 0; dt < 8; dt++) {
                o[dt][2*hf]     *= corr;
                o[dt][2*hf + 1] *= corr;
            }
        }

#pragma unroll
        for (int kc = 0; kc < 4; kc++) {
            unsigned pah[4], pal[4];
#pragma unroll
            for (int q = 0; q < 2; q++) {
                float x0 = s[2*kc + q][0], x1 = s[2*kc + q][1];
                float x2 = s[2*kc + q][2], x3 = s[2*kc + q][3];
                float h0 = bfhi(x0), h1 = bfhi(x1);
                float h2 = bfhi(x2), h3 = bfhi(x3);
                pah[2*q]     = pk2(x0, x1);
                pah[2*q + 1] = pk2(x2, x3);
                pal[2*q]     = pk2(x0 - h0, x1 - h1);
                pal[2*q + 1] = pk2(x2 - h2, x3 - h3);
            }
#pragma unroll
            for (int dtp = 0; dtp < 4; dtp++) {
                unsigned vbh[4], vbl[4];
                int vr = kc * 16 + (lane & 15);
                unsigned voff = vr * 128 +
                    (((unsigned)((2 * dtp + (lane >> 4)) ^ (vr & 7))) << 4);
                ldsm4t(vbh, sVh + voff);
                ldsm4t(vbl, sVl + voff);
                mma16816(o[2*dtp],   pah, vbh);
                mma16816(o[2*dtp],   pah, vbl);
                mma16816(o[2*dtp],   pal, vbh);
                mma16816(o[2*dtp+1], pah, vbh + 2);
                mma16816(o[2*dtp+1], pah, vbl + 2);
                mma16816(o[2*dtp+1], pal, vbh + 2);
            }
        }
    }

    // epilogue: normalize, write segmented bf16 hi/lo to g_aoa
    const int bb = bh >> 4, h = bh & 15;
    const float inv0 = 1.f / lr[0], inv1 = 1.f / lr[1];
    const int mrow0 = q0 + warp * 16 + g;
#pragma unroll
    for (int dt = 0; dt < 8; dt++) {
        int col = h * 64 + dt * 8 + 2 * t4;
        size_t seg = (size_t)(col >> 4) * 32 + (col & 15);
        size_t i0 = ((size_t)(bb * S_ + mrow0))     * 2048 + seg;
        size_t i1 = ((size_t)(bb * S_ + mrow0 + 8)) * 2048 + seg;
        float v0 = o[dt][0] * inv0, v1 = o[dt][1] * inv0;
        float w0 = o[dt][2] * inv1, w1 = o[dt][3] * inv1;
        float h0 = bfhi(v0), h1 = bfhi(v1), e0 = bfhi(w0), e1 = bfhi(w1);
        *(unsigned*)&g_aoa[i0]      = pk2(v0, v1);
        *(unsigned*)&g_aoa[i0 + 16] = pk2(v0 - h0, v1 - h1);
        *(unsigned*)&g_aoa[i1]      = pk2(w0, w1);
        *(unsigned*)&g_aoa[i1 + 16] = pk2(w0 - e0, w1 - e1);
    }
}

// ---------------------------------------------------------------------------
extern "C" void kernel_launch(void* const* d_in, const int* in_sizes, int n_in,
                              void* d_out, int out_size)
{
    (void)in_sizes; (void)n_in; (void)out_size;
    const float* x      = (const float*)d_in[0];
    const float* W_attn = (const float*)d_in[1];
    const float* b_attn = (const float*)d_in[2];
    const float* W_proj = (const float*)d_in[3];
    const float* b_proj = (const float*)d_in[4];
    float* out = (float*)d_out;

    conv_seg_x  <<<M_*C_/16/256, 256>>>(x);
    conv_plane<0><<<C_*N3_/8/256, 256>>>(W_attn);
    conv_plane<1><<<C_*C_/8/256,  256>>>(W_proj);
    tc_gemm2<N3_, true ><<<dim3(N3_/128, M_/128), 256>>>(b_attn, nullptr);
    flash_attn_tc<<<dim3(S_/64, B_*H_), 128>>>();
    tc_gemm2<C_,  false><<<dim3(C_/128,  M_/128), 256>>>(b_proj, out);
}